// round 9
// baseline (speedup 1.0000x reference)
#include <cuda_runtime.h>
#include <math.h>

#define BATCH 2048
#define STEPS 64
#define HID   64
#define NZv   32
#define INZ   32
#define DOUT  8
#define BT    14
#define NTHR  512
#define NCTA  ((BATCH + BT - 1) / BT)   /* 147 */

// -------- pre-transposed weight scratch (filled by prep_kernel each call) ----
__device__ float4 g_W0P4 [16 * 256];  // [m][o]: Wx0[o][4m+1..4m+4] (x=v for o<128 else c)
__device__ float  g_w0t  [256];       // Wx0[o][0]  (the t column)
__device__ float4 g_W1P4 [32 * 256];  // [m][o]: Wx1[o][4m..4m+3]
__device__ float4 g_Wv2P4[32 * 64];   // [m][o]: Wv2[o][4m..4m+3]
__device__ float  g_Wc2T [128 * 2048];// [k][n]  (n contiguous -> LDG.128 per k)
__device__ float  g_Wi0T [32  * 128];
__device__ float  g_Wi1T [128 * 128];
__device__ float  g_Wi2T [128 * 64];
__device__ float  g_b0   [256];       // [bv0 | bc0]
__device__ float  g_b1   [256];       // [bv1 | bc1]
__device__ float  g_WrT  [64 * 8];    // WrT[h][d]

__global__ void prep_kernel(const float* __restrict__ Wi0, const float* __restrict__ Wi1,
                            const float* __restrict__ Wi2,
                            const float* __restrict__ Wv0, const float* __restrict__ bv0,
                            const float* __restrict__ Wv1, const float* __restrict__ bv1,
                            const float* __restrict__ Wv2,
                            const float* __restrict__ Wc0, const float* __restrict__ bc0,
                            const float* __restrict__ Wc1, const float* __restrict__ bc1,
                            const float* __restrict__ Wc2, const float* __restrict__ Wr) {
    int tid = blockIdx.x * blockDim.x + threadIdx.x;
    int nt  = gridDim.x * blockDim.x;
    for (int i = tid; i < 16 * 256; i += nt) {
        int m = i >> 8, o = i & 255;
        const float* row = (o < 128) ? &Wv0[o * 65] : &Wc0[(o - 128) * 65];
        g_W0P4[i] = make_float4(row[4 * m + 1], row[4 * m + 2], row[4 * m + 3], row[4 * m + 4]);
    }
    for (int o = tid; o < 256; o += nt) {
        const float* row = (o < 128) ? &Wv0[o * 65] : &Wc0[(o - 128) * 65];
        g_w0t[o] = row[0];
        g_b0[o] = (o < 128) ? bv0[o] : bc0[o - 128];
        g_b1[o] = (o < 128) ? bv1[o] : bc1[o - 128];
    }
    for (int i = tid; i < 32 * 256; i += nt) {
        int m = i >> 8, o = i & 255;
        const float* row = (o < 128) ? &Wv1[o * 128] : &Wc1[(o - 128) * 128];
        g_W1P4[i] = make_float4(row[4 * m], row[4 * m + 1], row[4 * m + 2], row[4 * m + 3]);
    }
    for (int i = tid; i < 32 * 64; i += nt) {
        int m = i >> 6, o = i & 63;
        const float* row = &Wv2[o * 128];
        g_Wv2P4[i] = make_float4(row[4 * m], row[4 * m + 1], row[4 * m + 2], row[4 * m + 3]);
    }
    for (int i = tid; i < 128 * 2048; i += nt) {
        int k = i >> 11, n = i & 2047;
        g_Wc2T[i] = Wc2[n * 128 + k];
    }
    for (int i = tid; i < 32 * 128; i += nt) {
        int k = i >> 7, o = i & 127;
        g_Wi0T[i] = Wi0[o * 32 + k];
    }
    for (int i = tid; i < 128 * 128; i += nt) {
        int k = i >> 7, o = i & 127;
        g_Wi1T[i] = Wi1[o * 128 + k];
    }
    for (int i = tid; i < 128 * 64; i += nt) {
        int k = i >> 6, o = i & 63;
        g_Wi2T[i] = Wi2[o * 128 + k];
    }
    for (int i = tid; i < 64 * 8; i += nt) {
        int h = i >> 3, d = i & 7;
        g_WrT[i] = Wr[d * 64 + h];
    }
}

// fast, accurate-enough transcendentals (abs err ~1e-6)
__device__ __forceinline__ float tanh_fast(float x) {
    float e = __expf(2.0f * x);
    return 1.0f - __fdividef(2.0f, 1.0f + e);
}
__device__ __forceinline__ float lipswish(float x) {
    return 0.909f * __fdividef(x, 1.0f + __expf(-x));
}

#define PACK_DUP(out, w) \
    asm("mov.b64 %0, {%1, %1};" : "=l"(out) : "r"(__float_as_uint(w)))
#define PACK2(out, lo, hi) \
    asm("mov.b64 %0, {%1, %2};" : "=l"(out) : "r"(__float_as_uint(lo)), "r"(__float_as_uint(hi)))
#define UNPACK2(lo, hi, in) \
    do { unsigned int _ul, _uh; \
         asm("mov.b64 {%0, %1}, %2;" : "=r"(_ul), "=r"(_uh) : "l"(in)); \
         lo = __uint_as_float(_ul); hi = __uint_as_float(_uh); } while (0)
#define FMA2(acc, w2, a2) \
    asm("fma.rn.f32x2 %0, %1, %2, %0;" : "+l"(acc) : "l"(w2), "l"(a2))

__global__ void __launch_bounds__(NTHR, 1) sde_kernel(
    const float* __restrict__ ts, const float* __restrict__ init_noise,
    const float* __restrict__ bm,
    const float* __restrict__ bi0, const float* __restrict__ bi1, const float* __restrict__ bi2,
    const float* __restrict__ scale_v, const float* __restrict__ bv2,
    const float* __restrict__ scale_c, const float* __restrict__ bc2,
    const float* __restrict__ br, float* __restrict__ out)
{
    __shared__ float  y_s   [BT][64];     // current state
    __shared__ float  ynew_s[BT][64];     // y + drift
    __shared__ float  h1_s  [16][256];    // [hv1 | hc1]  (padded rows 14,15)
    __shared__ float  h2v_s [16][128];    // drift-path hidden2 (v half only)
    __shared__ float4 h2qd  [64][14];     // c-half hidden2, per-(kk,b) DUPLICATED pairs:
                                          // h2qd[kk][j] = {A[j][2kk],A[j][2kk],A[j][2kk+1],A[j][2kk+1]}
    __shared__ float  diff_s[64][17];     // diffusion increment, [h][b], padded
    __shared__ float4 bmq   [8][14];      // noise: bmq[q][j] = {bm[j][4q..4q+3]}

    const int tid  = threadIdx.x;
    const int b0g  = blockIdx.x * BT;
    int nb = BATCH - b0g; if (nb > BT) nb = BT;
    const float ts0 = ts[0];

    // step-invariant per-thread parameters (hoisted out of the time loop)
    const int oB  = tid & 255;            // output index for phases B/C
    const int gB  = tid >> 8;             // batch-group for B/C
    const int o64 = tid & 63;             // output index for phase D
    const int gD  = tid >> 6;
    const float w0t_r = g_w0t[oB];
    const float b0_r  = g_b0[oB];
    const float b1_r  = g_b1[oB];
    const float bv2_r = bv2[o64];
    const float sv_r  = scale_v[o64];
    const int   n0    = tid << 2;         // phase-E column base
    const float4 sc4  = *(const float4*)&scale_c[n0];
    const float4 bcv4 = *(const float4*)&bc2[n0];

    // ---------------- initial MLP: init_noise -> y0 ----------------
    {
        // FIX (R8 crash): stage init noise in h2qd (14336 floats), NOT bmq (448 floats).
        // The [16][32] staging view needs 512 floats; bmq overflowed by 256 B past the
        // end of the block's shared allocation -> illegal memory access.
        float* nbuf = (float*)h2qd;   // [16][32] staging, rows 14,15 zero-padded
        for (int i = tid; i < 16 * 32; i += NTHR) {
            int b = i >> 5, z = i & 31;
            nbuf[i] = (b < nb) ? init_noise[(size_t)(b0g + b) * INZ + z] : 0.0f;
        }
        __syncthreads();
        {   // L0: 32 -> 128, relu
            int o = tid & 127, g = tid >> 7;
            float acc[4];
            float bias = bi0[o];
            #pragma unroll
            for (int j = 0; j < 4; j++) acc[j] = bias;
            for (int k = 0; k < 32; k++) {
                float w = g_Wi0T[k * 128 + o];
                #pragma unroll
                for (int j = 0; j < 4; j++) acc[j] = fmaf(w, nbuf[(g * 4 + j) * 32 + k], acc[j]);
            }
            #pragma unroll
            for (int j = 0; j < 4; j++) h1_s[g * 4 + j][o] = fmaxf(acc[j], 0.0f);
        }
        __syncthreads();
        {   // L1: 128 -> 128, relu
            int o = tid & 127, g = tid >> 7;
            float acc[4];
            float bias = bi1[o];
            #pragma unroll
            for (int j = 0; j < 4; j++) acc[j] = bias;
            for (int k = 0; k < 128; k++) {
                float w = g_Wi1T[k * 128 + o];
                #pragma unroll
                for (int j = 0; j < 4; j++) acc[j] = fmaf(w, h1_s[g * 4 + j][k], acc[j]);
            }
            #pragma unroll
            for (int j = 0; j < 4; j++) h2v_s[g * 4 + j][o] = fmaxf(acc[j], 0.0f);
        }
        __syncthreads();
        {   // L2: 128 -> 64, identity -> y0
            int o = tid & 63, g = tid >> 6;
            float bias = bi2[o];
            float a0 = bias, a1 = bias;
            for (int k = 0; k < 128; k++) {
                float w = g_Wi2T[k * 64 + o];
                a0 = fmaf(w, h2v_s[g * 2 + 0][k], a0);
                a1 = fmaf(w, h2v_s[g * 2 + 1][k], a1);
            }
            if (g * 2 + 0 < BT) y_s[g * 2 + 0][o] = a0;
            if (g * 2 + 1 < BT) y_s[g * 2 + 1][o] = a1;
        }
        __syncthreads();
    }

    // ---------------- time scan ----------------
    for (int step = 0; step < STEPS; step++) {
        // stage noise for this step: bmq[z>>2][b].comp[z&3] = bm[b][z]
        for (int i = tid; i < BT * 32; i += NTHR) {
            int b = i >> 5, z = i & 31;
            float v = (b < nb)
                ? bm[(size_t)(b0g + b) * (STEPS * NZv) + step * NZv + z] : 0.0f;
            ((float*)&bmq[z >> 2][b])[z & 3] = v;
        }
        // ---- phase B: layer0 of v & c paths (256 outputs, K=65) ----
        {
            const int bb = gB * 7;
            float tcur = ts0 + (float)step;
            float bias = fmaf(w0t_r, tcur, b0_r);
            unsigned long long acc2[7];
            #pragma unroll
            for (int j = 0; j < 7; j++) PACK2(acc2[j], bias, 0.0f);
            const ulonglong2* wp = ((const ulonglong2*)g_W0P4) + oB;
            #pragma unroll 4
            for (int m = 0; m < 16; m++) {
                ulonglong2 w = wp[m * 256];
                #pragma unroll
                for (int j = 0; j < 7; j++) {
                    ulonglong2 a = *(const ulonglong2*)&y_s[bb + j][4 * m];
                    FMA2(acc2[j], w.x, a.x);
                    FMA2(acc2[j], w.y, a.y);
                }
            }
            #pragma unroll
            for (int j = 0; j < 7; j++) {
                float lo, hi; UNPACK2(lo, hi, acc2[j]);
                h1_s[bb + j][oB] = lipswish(lo + hi);
            }
        }
        __syncthreads();
        // ---- phase C: layer1 of v & c paths (256 outputs, K=128) ----
        {
            const int bb = gB * 7;
            const int koff = (oB < 128) ? 0 : 128;
            unsigned long long acc2[7];
            #pragma unroll
            for (int j = 0; j < 7; j++) PACK2(acc2[j], b1_r, 0.0f);
            const ulonglong2* wp = ((const ulonglong2*)g_W1P4) + oB;
            #pragma unroll 4
            for (int m = 0; m < 32; m++) {
                ulonglong2 w = wp[m * 256];
                #pragma unroll
                for (int j = 0; j < 7; j++) {
                    ulonglong2 a = *(const ulonglong2*)&h1_s[bb + j][koff + 4 * m];
                    FMA2(acc2[j], w.x, a.x);
                    FMA2(acc2[j], w.y, a.y);
                }
            }
            if (oB < 128) {
                #pragma unroll
                for (int j = 0; j < 7; j++) {
                    float lo, hi; UNPACK2(lo, hi, acc2[j]);
                    h2v_s[bb + j][oB] = lipswish(lo + hi);
                }
            } else {
                // duplicated write for phase E: k = oB-128, slot pos = k&1
                int k = oB - 128, kk = k >> 1, pos = k & 1;
                #pragma unroll
                for (int j = 0; j < 7; j++) {
                    float lo, hi; UNPACK2(lo, hi, acc2[j]);
                    float v = lipswish(lo + hi);
                    unsigned long long vv; PACK_DUP(vv, v);
                    *(unsigned long long*)((char*)&h2qd[kk][bb + j] + pos * 8) = vv;
                }
            }
        }
        __syncthreads();
        // ---- phase D: drift head (64 outputs, K=128) -> ynew = y + scale_v*tanh ----
        {
            unsigned long long acc0, acc1;
            PACK2(acc0, bv2_r, 0.0f);
            PACK2(acc1, bv2_r, 0.0f);
            const ulonglong2* wp = ((const ulonglong2*)g_Wv2P4) + o64;
            #pragma unroll 4
            for (int m = 0; m < 32; m++) {
                ulonglong2 w = wp[m * 64];
                ulonglong2 x0 = *(const ulonglong2*)&h2v_s[gD * 2 + 0][4 * m];
                ulonglong2 x1 = *(const ulonglong2*)&h2v_s[gD * 2 + 1][4 * m];
                FMA2(acc0, w.x, x0.x); FMA2(acc0, w.y, x0.y);
                FMA2(acc1, w.x, x1.x); FMA2(acc1, w.y, x1.y);
            }
            float l0, h0, l1, h1;
            UNPACK2(l0, h0, acc0);
            UNPACK2(l1, h1, acc1);
            int bb = gD * 2;
            if (bb + 0 < BT) ynew_s[bb + 0][o64] = y_s[bb + 0][o64] + sv_r * tanh_fast(l0 + h0);
            if (bb + 1 < BT) ynew_s[bb + 1][o64] = y_s[bb + 1][o64] + sv_r * tanh_fast(l1 + h1);
        }
        // ---- phase E: controlled field, n-paired f32x2: weights load as natural pairs,
        //      activations pre-duplicated in smem -> zero packing movs in the hot loop ----
        {
            unsigned long long acc2[2][14];   // [n-pair p][batch j]
            #pragma unroll
            for (int p = 0; p < 2; p++)
                #pragma unroll
                for (int j = 0; j < 14; j++) acc2[p][j] = 0ULL;

            const float4* wrow = ((const float4*)g_Wc2T) + tid;   // + k*512 per row
            ulonglong2 wbufA[2], wbufB[2];
            wbufA[0] = __ldcg((const ulonglong2*)(wrow + 0 * 512));
            wbufB[0] = __ldcg((const ulonglong2*)(wrow + 1 * 512));
            wbufA[1] = __ldcg((const ulonglong2*)(wrow + 2 * 512));
            wbufB[1] = __ldcg((const ulonglong2*)(wrow + 3 * 512));
            #pragma unroll 2
            for (int kk = 0; kk < 64; kk++) {
                ulonglong2 wA = wbufA[kk & 1];
                ulonglong2 wB = wbufB[kk & 1];
                if (kk < 62) {
                    wbufA[kk & 1] = __ldcg((const ulonglong2*)(wrow + (size_t)(2 * kk + 4) * 512));
                    wbufB[kk & 1] = __ldcg((const ulonglong2*)(wrow + (size_t)(2 * kk + 5) * 512));
                }
                #pragma unroll
                for (int j = 0; j < 14; j++) {
                    ulonglong2 a = *(const ulonglong2*)&h2qd[kk][j];
                    FMA2(acc2[0][j], wA.x, a.x);   // n0,n1 x k=2kk
                    FMA2(acc2[0][j], wB.x, a.y);   // n0,n1 x k=2kk+1
                    FMA2(acc2[1][j], wA.y, a.x);   // n2,n3 x k=2kk
                    FMA2(acc2[1][j], wB.y, a.y);   // n2,n3 x k=2kk+1
                }
            }
            // epilogue: bias + tanh + scale + noise
            float s[14];
            const int q = tid & 7;
            #pragma unroll
            for (int j = 0; j < 14; j++) {
                float4 bmv = bmq[q][j];
                float z0, z1, z2, z3;
                UNPACK2(z0, z1, acc2[0][j]);
                UNPACK2(z2, z3, acc2[1][j]);
                float t0 = sc4.x * tanh_fast(z0 + bcv4.x);
                float t1 = sc4.y * tanh_fast(z1 + bcv4.y);
                float t2 = sc4.z * tanh_fast(z2 + bcv4.z);
                float t3 = sc4.w * tanh_fast(z3 + bcv4.w);
                s[j] = fmaf(t0, bmv.x, fmaf(t1, bmv.y, fmaf(t2, bmv.z, t3 * bmv.w)));
            }
            // reduce across the 8-lane group that shares h = tid>>3
            #pragma unroll
            for (int off = 1; off <= 4; off <<= 1) {
                #pragma unroll
                for (int j = 0; j < 14; j++)
                    s[j] += __shfl_xor_sync(0xffffffffu, s[j], off);
            }
            if ((tid & 7) == 0) {
                int h = tid >> 3;
                #pragma unroll
                for (int j = 0; j < 14; j++) diff_s[h][j] = s[j];
            }
        }
        __syncthreads();
        // ---- phase F: y update ----
        for (int i = tid; i < BT * 64; i += NTHR) {
            int b = i >> 6, h = i & 63;
            y_s[b][h] = ynew_s[b][h] + diff_s[h][b];
        }
        __syncthreads();
        // ---- readout: out[b, step, :] = y @ Wr^T + br ----
        if (tid < BT * DOUT) {
            int b = tid >> 3, d = tid & 7;
            if (b < nb) {
                float acc = br[d];
                #pragma unroll 8
                for (int h = 0; h < 64; h++)
                    acc = fmaf(y_s[b][h], g_WrT[h * 8 + d], acc);
                out[(size_t)(b0g + b) * (STEPS * DOUT) + step * DOUT + d] = acc;
            }
        }
    }
}

extern "C" void kernel_launch(void* const* d_in, const int* in_sizes, int n_in,
                              void* d_out, int out_size) {
    (void)in_sizes; (void)n_in; (void)out_size;
    const float* ts         = (const float*)d_in[0];
    const float* init_noise = (const float*)d_in[1];
    const float* bm         = (const float*)d_in[2];
    const float* Wi0        = (const float*)d_in[3];
    const float* bi0        = (const float*)d_in[4];
    const float* Wi1        = (const float*)d_in[5];
    const float* bi1        = (const float*)d_in[6];
    const float* Wi2        = (const float*)d_in[7];
    const float* bi2        = (const float*)d_in[8];
    const float* scale_v    = (const float*)d_in[9];
    const float* Wv0        = (const float*)d_in[10];
    const float* bv0        = (const float*)d_in[11];
    const float* Wv1        = (const float*)d_in[12];
    const float* bv1        = (const float*)d_in[13];
    const float* Wv2        = (const float*)d_in[14];
    const float* bv2        = (const float*)d_in[15];
    const float* scale_c    = (const float*)d_in[16];
    const float* Wc0        = (const float*)d_in[17];
    const float* bc0        = (const float*)d_in[18];
    const float* Wc1        = (const float*)d_in[19];
    const float* bc1        = (const float*)d_in[20];
    const float* Wc2        = (const float*)d_in[21];
    const float* bc2        = (const float*)d_in[22];
    const float* Wr         = (const float*)d_in[23];
    const float* br         = (const float*)d_in[24];
    float* out = (float*)d_out;

    prep_kernel<<<256, 256>>>(Wi0, Wi1, Wi2, Wv0, bv0, Wv1, bv1, Wv2,
                              Wc0, bc0, Wc1, bc1, Wc2, Wr);
    sde_kernel<<<NCTA, NTHR>>>(ts, init_noise, bm, bi0, bi1, bi2,
                               scale_v, bv2, scale_c, bc2, br, out);
}

// round 10
// speedup vs baseline: 1.7861x; 1.7861x over previous
#include <cuda_runtime.h>
#include <cuda_bf16.h>
#include <math.h>

#define BATCH 2048
#define STEPS 64
#define HID   64
#define NZv   32
#define INZ   32
#define DOUT  8
#define BT    14
#define NTHR  512
#define NCTA  ((BATCH + BT - 1) / BT)   /* 147 */

// -------- pre-transposed weight scratch (filled by prep_kernel each call) ----
__device__ float4 g_W0P4 [16 * 256];  // [m][o]: Wx0[o][4m+1..4m+4] (x=v for o<128 else c)
__device__ float  g_w0t  [256];       // Wx0[o][0]  (the t column)
__device__ float4 g_W1P4 [32 * 256];  // [m][o]: Wx1[o][4m..4m+3]
__device__ float4 g_Wv2P4[32 * 64];   // [m][o]: Wv2[o][4m..8m+3]
__device__ uint4  g_WcFrag[256 * 8 * 32]; // mma B-fragments: [ntile][ktile][lane] = {b0h,b1h,b0l,b1l}
__device__ float  g_Wi0T [32  * 128];
__device__ float  g_Wi1T [128 * 128];
__device__ float  g_Wi2T [128 * 64];
__device__ float  g_b0   [256];       // [bv0 | bc0]
__device__ float  g_b1   [256];       // [bv1 | bc1]
__device__ float  g_WrT  [64 * 8];    // WrT[h][d]

__device__ __forceinline__ unsigned short bf16_hi(float v) {
    __nv_bfloat16 h = __float2bfloat16(v);
    return __bfloat16_as_ushort(h);
}
__device__ __forceinline__ unsigned short bf16_lo(float v) {
    __nv_bfloat16 h = __float2bfloat16(v);
    float r = v - __bfloat162float(h);
    __nv_bfloat16 l = __float2bfloat16(r);
    return __bfloat16_as_ushort(l);
}

__global__ void prep_kernel(const float* __restrict__ Wi0, const float* __restrict__ Wi1,
                            const float* __restrict__ Wi2,
                            const float* __restrict__ Wv0, const float* __restrict__ bv0,
                            const float* __restrict__ Wv1, const float* __restrict__ bv1,
                            const float* __restrict__ Wv2,
                            const float* __restrict__ Wc0, const float* __restrict__ bc0,
                            const float* __restrict__ Wc1, const float* __restrict__ bc1,
                            const float* __restrict__ Wc2, const float* __restrict__ Wr) {
    int tid = blockIdx.x * blockDim.x + threadIdx.x;
    int nt  = gridDim.x * blockDim.x;
    for (int i = tid; i < 16 * 256; i += nt) {
        int m = i >> 8, o = i & 255;
        const float* row = (o < 128) ? &Wv0[o * 65] : &Wc0[(o - 128) * 65];
        g_W0P4[i] = make_float4(row[4 * m + 1], row[4 * m + 2], row[4 * m + 3], row[4 * m + 4]);
    }
    for (int o = tid; o < 256; o += nt) {
        const float* row = (o < 128) ? &Wv0[o * 65] : &Wc0[(o - 128) * 65];
        g_w0t[o] = row[0];
        g_b0[o] = (o < 128) ? bv0[o] : bc0[o - 128];
        g_b1[o] = (o < 128) ? bv1[o] : bc1[o - 128];
    }
    for (int i = tid; i < 32 * 256; i += nt) {
        int m = i >> 8, o = i & 255;
        const float* row = (o < 128) ? &Wv1[o * 128] : &Wc1[(o - 128) * 128];
        g_W1P4[i] = make_float4(row[4 * m], row[4 * m + 1], row[4 * m + 2], row[4 * m + 3]);
    }
    for (int i = tid; i < 32 * 64; i += nt) {
        int m = i >> 6, o = i & 63;
        const float* row = &Wv2[o * 128];
        g_Wv2P4[i] = make_float4(row[4 * m], row[4 * m + 1], row[4 * m + 2], row[4 * m + 3]);
    }
    // mma B-fragments for Wc2 (bf16 hi/lo split).
    // ntg = n-tile (8 cols), kt = k-tile (16 rows of k). For lane:
    //   n  = ntg*8 + (lane>>2), t = lane&3, k0 = kt*16 + 2t
    //   b0 = {B[k0][n], B[k0+1][n]} (lower k in low 16 bits), b1 = same at k0+8
    for (int i = tid; i < 256 * 8 * 32; i += nt) {
        int lane = i & 31, kt = (i >> 5) & 7, ntg = i >> 8;
        int n = ntg * 8 + (lane >> 2);
        int t = lane & 3;
        int k0 = kt * 16 + 2 * t;
        const float* wr = Wc2 + (size_t)n * 128;
        float w00 = wr[k0],     w01 = wr[k0 + 1];
        float w10 = wr[k0 + 8], w11 = wr[k0 + 9];
        uint4 f;
        f.x = (unsigned)bf16_hi(w00) | ((unsigned)bf16_hi(w01) << 16);
        f.y = (unsigned)bf16_hi(w10) | ((unsigned)bf16_hi(w11) << 16);
        f.z = (unsigned)bf16_lo(w00) | ((unsigned)bf16_lo(w01) << 16);
        f.w = (unsigned)bf16_lo(w10) | ((unsigned)bf16_lo(w11) << 16);
        g_WcFrag[i] = f;
    }
    for (int i = tid; i < 32 * 128; i += nt) {
        int k = i >> 7, o = i & 127;
        g_Wi0T[i] = Wi0[o * 32 + k];
    }
    for (int i = tid; i < 128 * 128; i += nt) {
        int k = i >> 7, o = i & 127;
        g_Wi1T[i] = Wi1[o * 128 + k];
    }
    for (int i = tid; i < 128 * 64; i += nt) {
        int k = i >> 6, o = i & 63;
        g_Wi2T[i] = Wi2[o * 128 + k];
    }
    for (int i = tid; i < 64 * 8; i += nt) {
        int h = i >> 3, d = i & 7;
        g_WrT[i] = Wr[d * 64 + h];
    }
}

// fast, accurate-enough transcendentals (abs err ~1e-6)
__device__ __forceinline__ float tanh_fast(float x) {
    float e = __expf(2.0f * x);
    return 1.0f - __fdividef(2.0f, 1.0f + e);
}
__device__ __forceinline__ float lipswish(float x) {
    return 0.909f * __fdividef(x, 1.0f + __expf(-x));
}

#define PACK2(out, lo, hi) \
    asm("mov.b64 %0, {%1, %2};" : "=l"(out) : "r"(__float_as_uint(lo)), "r"(__float_as_uint(hi)))
#define UNPACK2(lo, hi, in) \
    do { unsigned int _ul, _uh; \
         asm("mov.b64 {%0, %1}, %2;" : "=r"(_ul), "=r"(_uh) : "l"(in)); \
         lo = __uint_as_float(_ul); hi = __uint_as_float(_uh); } while (0)
#define FMA2(acc, w2, a2) \
    asm("fma.rn.f32x2 %0, %1, %2, %0;" : "+l"(acc) : "l"(w2), "l"(a2))

#define LDSM4(r0, r1, r2, r3, addr) \
    asm volatile("ldmatrix.sync.aligned.m8n8.x4.shared.b16 {%0,%1,%2,%3}, [%4];" \
        : "=r"(r0), "=r"(r1), "=r"(r2), "=r"(r3) : "r"(addr))

#define MMA_BF16(d, a0, a1, a2, a3, b0, b1) \
    asm volatile("mma.sync.aligned.m16n8k16.row.col.f32.bf16.bf16.f32 " \
        "{%0,%1,%2,%3}, {%4,%5,%6,%7}, {%8,%9}, {%0,%1,%2,%3};" \
        : "+f"(d[0]), "+f"(d[1]), "+f"(d[2]), "+f"(d[3]) \
        : "r"(a0), "r"(a1), "r"(a2), "r"(a3), "r"(b0), "r"(b1))

__global__ void __launch_bounds__(NTHR, 1) sde_kernel(
    const float* __restrict__ ts, const float* __restrict__ init_noise,
    const float* __restrict__ bm,
    const float* __restrict__ bi0, const float* __restrict__ bi1, const float* __restrict__ bi2,
    const float* __restrict__ scale_v, const float* __restrict__ bv2,
    const float* __restrict__ scale_c, const float* __restrict__ bc2,
    const float* __restrict__ br, float* __restrict__ out)
{
    __shared__ float  y_s   [BT][64];
    __shared__ float  ynew_s[BT][64];
    __shared__ float  h1_s  [16][256];          // [hv1 | hc1]
    __shared__ float  h2v_s [16][128];          // drift-path hidden2 (v half)
    __shared__ unsigned short Ahi_s[16][136];   // c-half hidden2 bf16 hi ([batch][k], 272B rows)
    __shared__ unsigned short Alo_s[16][136];   // bf16 lo
    __shared__ float  diff_s[64][17];
    __shared__ float  bm_s  [16][33];           // noise [b][nz]

    const int tid  = threadIdx.x;
    const int b0g  = blockIdx.x * BT;
    int nb = BATCH - b0g; if (nb > BT) nb = BT;
    const float ts0 = ts[0];

    const int oB  = tid & 255;
    const int gB  = tid >> 8;
    const int o64 = tid & 63;
    const int gD  = tid >> 6;
    const float w0t_r = g_w0t[oB];
    const float b0_r  = g_b0[oB];
    const float b1_r  = g_b1[oB];
    const float bv2_r = bv2[o64];
    const float sv_r  = scale_v[o64];

    // phase-E per-thread constants
    const int lane = tid & 31;
    const int wrp  = tid >> 5;                 // warp 0..15, n-slice [wrp*128, wrp*128+128)
    const int lrow = lane & 15;                // ldmatrix row
    const int kofs = (lane & 16) ? 8 : 0;      // ldmatrix k-half
    const unsigned aHiBase = (unsigned)__cvta_generic_to_shared(&Ahi_s[0][0]) + (lrow * 136 + kofs) * 2;
    const unsigned aLoBase = (unsigned)__cvta_generic_to_shared(&Alo_s[0][0]) + (lrow * 136 + kofs) * 2;

    // zero ldmatrix pad rows 14,15 (batches 14,15 don't exist)
    if (tid < 272) {
        int r = 14 + tid / 136, c = tid % 136;
        Ahi_s[r][c] = 0; Alo_s[r][c] = 0;
    }

    // ---------------- initial MLP: init_noise -> y0 ----------------
    {
        float* nbuf = (float*)h2v_s;   // [16][32] staging (512 floats, fits in h2v_s)
        for (int i = tid; i < 16 * 32; i += NTHR) {
            int b = i >> 5, z = i & 31;
            nbuf[i] = (b < nb) ? init_noise[(size_t)(b0g + b) * INZ + z] : 0.0f;
        }
        __syncthreads();
        {   // L0: 32 -> 128, relu
            int o = tid & 127, g = tid >> 7;
            float acc[4];
            float bias = bi0[o];
            #pragma unroll
            for (int j = 0; j < 4; j++) acc[j] = bias;
            for (int k = 0; k < 32; k++) {
                float w = g_Wi0T[k * 128 + o];
                #pragma unroll
                for (int j = 0; j < 4; j++) acc[j] = fmaf(w, nbuf[(g * 4 + j) * 32 + k], acc[j]);
            }
            #pragma unroll
            for (int j = 0; j < 4; j++) h1_s[g * 4 + j][o] = fmaxf(acc[j], 0.0f);
        }
        __syncthreads();
        {   // L1: 128 -> 128, relu  (overwrites nbuf region, reads h1_s)
            int o = tid & 127, g = tid >> 7;
            float acc[4];
            float bias = bi1[o];
            #pragma unroll
            for (int j = 0; j < 4; j++) acc[j] = bias;
            for (int k = 0; k < 128; k++) {
                float w = g_Wi1T[k * 128 + o];
                #pragma unroll
                for (int j = 0; j < 4; j++) acc[j] = fmaf(w, h1_s[g * 4 + j][k], acc[j]);
            }
            __syncthreads();   // nbuf fully consumed before overwrite
            #pragma unroll
            for (int j = 0; j < 4; j++) h2v_s[g * 4 + j][o] = fmaxf(acc[j], 0.0f);
        }
        __syncthreads();
        {   // L2: 128 -> 64, identity -> y0
            int o = tid & 63, g = tid >> 6;
            float bias = bi2[o];
            float a0 = bias, a1 = bias;
            for (int k = 0; k < 128; k++) {
                float w = g_Wi2T[k * 64 + o];
                a0 = fmaf(w, h2v_s[g * 2 + 0][k], a0);
                a1 = fmaf(w, h2v_s[g * 2 + 1][k], a1);
            }
            if (g * 2 + 0 < BT) y_s[g * 2 + 0][o] = a0;
            if (g * 2 + 1 < BT) y_s[g * 2 + 1][o] = a1;
        }
        __syncthreads();
    }

    // ---------------- time scan ----------------
    for (int step = 0; step < STEPS; step++) {
        // stage noise
        for (int i = tid; i < BT * 32; i += NTHR) {
            int b = i >> 5, z = i & 31;
            bm_s[b][z] = (b < nb)
                ? bm[(size_t)(b0g + b) * (STEPS * NZv) + step * NZv + z] : 0.0f;
        }
        // ---- phase B: layer0 of v & c paths (256 outputs, K=65), f32x2 ----
        {
            const int bb = gB * 7;
            float tcur = ts0 + (float)step;
            float bias = fmaf(w0t_r, tcur, b0_r);
            unsigned long long acc2[7];
            #pragma unroll
            for (int j = 0; j < 7; j++) PACK2(acc2[j], bias, 0.0f);
            const ulonglong2* wp = ((const ulonglong2*)g_W0P4) + oB;
            #pragma unroll 4
            for (int m = 0; m < 16; m++) {
                ulonglong2 w = wp[m * 256];
                #pragma unroll
                for (int j = 0; j < 7; j++) {
                    ulonglong2 a = *(const ulonglong2*)&y_s[bb + j][4 * m];
                    FMA2(acc2[j], w.x, a.x);
                    FMA2(acc2[j], w.y, a.y);
                }
            }
            #pragma unroll
            for (int j = 0; j < 7; j++) {
                float lo, hi; UNPACK2(lo, hi, acc2[j]);
                h1_s[bb + j][oB] = lipswish(lo + hi);
            }
        }
        __syncthreads();
        // ---- phase C: layer1 of v & c paths (256 outputs, K=128), f32x2 ----
        {
            const int bb = gB * 7;
            const int koff = (oB < 128) ? 0 : 128;
            unsigned long long acc2[7];
            #pragma unroll
            for (int j = 0; j < 7; j++) PACK2(acc2[j], b1_r, 0.0f);
            const ulonglong2* wp = ((const ulonglong2*)g_W1P4) + oB;
            #pragma unroll 4
            for (int m = 0; m < 32; m++) {
                ulonglong2 w = wp[m * 256];
                #pragma unroll
                for (int j = 0; j < 7; j++) {
                    ulonglong2 a = *(const ulonglong2*)&h1_s[bb + j][koff + 4 * m];
                    FMA2(acc2[j], w.x, a.x);
                    FMA2(acc2[j], w.y, a.y);
                }
            }
            if (oB < 128) {
                #pragma unroll
                for (int j = 0; j < 7; j++) {
                    float lo, hi; UNPACK2(lo, hi, acc2[j]);
                    h2v_s[bb + j][oB] = lipswish(lo + hi);
                }
            } else {
                // c-half -> bf16 hi/lo activation tiles for the mma phase
                int k = oB - 128;
                #pragma unroll
                for (int j = 0; j < 7; j++) {
                    float lo, hi; UNPACK2(lo, hi, acc2[j]);
                    float v = lipswish(lo + hi);
                    Ahi_s[bb + j][k] = bf16_hi(v);
                    Alo_s[bb + j][k] = bf16_lo(v);
                }
            }
        }
        __syncthreads();
        // ---- phase D: drift head (64 outputs, K=128), f32x2 ----
        {
            unsigned long long acc0, acc1;
            PACK2(acc0, bv2_r, 0.0f);
            PACK2(acc1, bv2_r, 0.0f);
            const ulonglong2* wp = ((const ulonglong2*)g_Wv2P4) + o64;
            #pragma unroll 4
            for (int m = 0; m < 32; m++) {
                ulonglong2 w = wp[m * 64];
                ulonglong2 x0 = *(const ulonglong2*)&h2v_s[gD * 2 + 0][4 * m];
                ulonglong2 x1 = *(const ulonglong2*)&h2v_s[gD * 2 + 1][4 * m];
                FMA2(acc0, w.x, x0.x); FMA2(acc0, w.y, x0.y);
                FMA2(acc1, w.x, x1.x); FMA2(acc1, w.y, x1.y);
            }
            float l0, h0, l1, h1;
            UNPACK2(l0, h0, acc0);
            UNPACK2(l1, h1, acc1);
            int bb = gD * 2;
            if (bb + 0 < BT) ynew_s[bb + 0][o64] = y_s[bb + 0][o64] + sv_r * tanh_fast(l0 + h0);
            if (bb + 1 < BT) ynew_s[bb + 1][o64] = y_s[bb + 1][o64] + sv_r * tanh_fast(l1 + h1);
        }
        // ---- phase E: controlled field via mma.sync bf16 hi/lo (z = AhWh + AhWl + AlWh) ----
        {
            const int t = lane & 3, g = lane >> 2;
            #pragma unroll
            for (int blk = 0; blk < 4; blk++) {      // h = 4*wrp + blk
                float acc[4][4];
                #pragma unroll
                for (int q = 0; q < 4; q++)
                    #pragma unroll
                    for (int r = 0; r < 4; r++) acc[q][r] = 0.0f;

                const uint4* wp = g_WcFrag + ((size_t)(wrp * 16 + blk * 4) * 8) * 32 + lane;
                #pragma unroll
                for (int kt = 0; kt < 8; kt++) {
                    unsigned ah0, ah1, ah2, ah3, al0, al1, al2, al3;
                    LDSM4(ah0, ah1, ah2, ah3, aHiBase + kt * 32);
                    LDSM4(al0, al1, al2, al3, aLoBase + kt * 32);
                    #pragma unroll
                    for (int q = 0; q < 4; q++) {
                        uint4 W = __ldcg(wp + q * 256 + kt * 32);
                        MMA_BF16(acc[q], ah0, ah1, ah2, ah3, W.x, W.y);   // Ah*Wh
                        MMA_BF16(acc[q], ah0, ah1, ah2, ah3, W.z, W.w);   // Ah*Wl
                        MMA_BF16(acc[q], al0, al1, al2, al3, W.x, W.y);   // Al*Wh
                    }
                }
                // epilogue: z -> tanh -> scale -> noise-weighted partial sums
                float s0 = 0.0f, s1 = 0.0f;
                #pragma unroll
                for (int q = 0; q < 4; q++) {
                    int n0 = (wrp * 16 + blk * 4 + q) * 8 + 2 * t;   // cols n0, n0+1
                    float2 sc = __ldg((const float2*)&scale_c[n0]);
                    float2 bc = __ldg((const float2*)&bc2[n0]);
                    int nz0 = n0 & 31;
                    float t0 = sc.x * tanh_fast(acc[q][0] + bc.x);
                    float t1 = sc.y * tanh_fast(acc[q][1] + bc.y);
                    float t2 = sc.x * tanh_fast(acc[q][2] + bc.x);
                    float t3 = sc.y * tanh_fast(acc[q][3] + bc.y);
                    s0 = fmaf(t0, bm_s[g][nz0],     fmaf(t1, bm_s[g][nz0 + 1],     s0));
                    s1 = fmaf(t2, bm_s[g + 8][nz0], fmaf(t3, bm_s[g + 8][nz0 + 1], s1));
                }
                // reduce over t lanes (cols within the h-group)
                s0 += __shfl_xor_sync(0xffffffffu, s0, 1);
                s0 += __shfl_xor_sync(0xffffffffu, s0, 2);
                s1 += __shfl_xor_sync(0xffffffffu, s1, 1);
                s1 += __shfl_xor_sync(0xffffffffu, s1, 2);
                if (t == 0) {
                    int h = 4 * wrp + blk;
                    diff_s[h][g] = s0;                 // batches 0..7
                    if (g < 6) diff_s[h][g + 8] = s1;  // batches 8..13
                }
            }
        }
        __syncthreads();
        // ---- phase F: y update ----
        for (int i = tid; i < BT * 64; i += NTHR) {
            int b = i >> 6, h = i & 63;
            y_s[b][h] = ynew_s[b][h] + diff_s[h][b];
        }
        __syncthreads();
        // ---- readout: out[b, step, :] = y @ Wr^T + br ----
        if (tid < BT * DOUT) {
            int b = tid >> 3, d = tid & 7;
            if (b < nb) {
                float acc = br[d];
                #pragma unroll 8
                for (int h = 0; h < 64; h++)
                    acc = fmaf(y_s[b][h], g_WrT[h * 8 + d], acc);
                out[(size_t)(b0g + b) * (STEPS * DOUT) + step * DOUT + d] = acc;
            }
        }
    }
}

extern "C" void kernel_launch(void* const* d_in, const int* in_sizes, int n_in,
                              void* d_out, int out_size) {
    (void)in_sizes; (void)n_in; (void)out_size;
    const float* ts         = (const float*)d_in[0];
    const float* init_noise = (const float*)d_in[1];
    const float* bm         = (const float*)d_in[2];
    const float* Wi0        = (const float*)d_in[3];
    const float* bi0        = (const float*)d_in[4];
    const float* Wi1        = (const float*)d_in[5];
    const float* bi1        = (const float*)d_in[6];
    const float* Wi2        = (const float*)d_in[7];
    const float* bi2        = (const float*)d_in[8];
    const float* scale_v    = (const float*)d_in[9];
    const float* Wv0        = (const float*)d_in[10];
    const float* bv0        = (const float*)d_in[11];
    const float* Wv1        = (const float*)d_in[12];
    const float* bv1        = (const float*)d_in[13];
    const float* Wv2        = (const float*)d_in[14];
    const float* bv2        = (const float*)d_in[15];
    const float* scale_c    = (const float*)d_in[16];
    const float* Wc0        = (const float*)d_in[17];
    const float* bc0        = (const float*)d_in[18];
    const float* Wc1        = (const float*)d_in[19];
    const float* bc1        = (const float*)d_in[20];
    const float* Wc2        = (const float*)d_in[21];
    const float* bc2        = (const float*)d_in[22];
    const float* Wr         = (const float*)d_in[23];
    const float* br         = (const float*)d_in[24];
    float* out = (float*)d_out;

    prep_kernel<<<256, 256>>>(Wi0, Wi1, Wi2, Wv0, bv0, Wv1, bv1, Wv2,
                              Wc0, bc0, Wc1, bc1, Wc2, Wr);
    sde_kernel<<<NCTA, NTHR>>>(ts, init_noise, bm, bi0, bi1, bi2,
                               scale_v, bv2, scale_c, bc2, br, out);
}

// round 12
// speedup vs baseline: 2.7914x; 1.5628x over previous
#include <cuda_runtime.h>
#include <cuda_bf16.h>
#include <math.h>

#define BATCH 2048
#define STEPS 64
#define HID   64
#define NZv   32
#define INZ   32
#define DOUT  8
#define BT    14
#define NTHR  512
#define NCTA  ((BATCH + BT - 1) / BT)   /* 147 */

// -------- weight scratch (filled by prep_kernel each call) ----
// mma B-fragments, [ntile][ktile][lane] = {b0h,b1h,b0l,b1l} (bf16 hi/lo split)
__device__ uint4  g_W0Frag [32 * 4 * 32];   // [Wv0|Wc0], K=64 (y part; t col in epilogue)
__device__ uint4  g_W1Frag [32 * 8 * 32];   // [Wv1|Wc1], K=128
__device__ uint4  g_Wv2Frag[ 8 * 8 * 32];   // Wv2, K=128
__device__ uint4  g_WcFrag [256 * 8 * 32];  // Wc2, K=128
__device__ float  g_Wi0T [32  * 128];
__device__ float  g_Wi1T [128 * 128];
__device__ float  g_Wi2T [128 * 64];
__device__ float  g_w0t  [256];             // Wx0[o][0]  (t column)
__device__ float  g_b0   [256];             // [bv0 | bc0]
__device__ float  g_b1   [256];             // [bv1 | bc1]
__device__ float  g_WrT  [64 * 8];          // WrT[h][d]

__device__ __forceinline__ unsigned short bf16_hi_u(float v) {
    return __bfloat16_as_ushort(__float2bfloat16(v));
}
__device__ __forceinline__ unsigned short bf16_lo_u(float v) {
    __nv_bfloat16 h = __float2bfloat16(v);
    return __bfloat16_as_ushort(__float2bfloat16(v - __bfloat162float(h)));
}

__global__ void prep_kernel(const float* __restrict__ Wi0, const float* __restrict__ Wi1,
                            const float* __restrict__ Wi2,
                            const float* __restrict__ Wv0, const float* __restrict__ bv0,
                            const float* __restrict__ Wv1, const float* __restrict__ bv1,
                            const float* __restrict__ Wv2,
                            const float* __restrict__ Wc0, const float* __restrict__ bc0,
                            const float* __restrict__ Wc1, const float* __restrict__ bc1,
                            const float* __restrict__ Wc2, const float* __restrict__ Wr) {
    int tid = blockIdx.x * blockDim.x + threadIdx.x;
    int nt  = gridDim.x * blockDim.x;
    // W0 frags (K=64, source cols shifted by 1 for the t column)
    for (int i = tid; i < 32 * 4 * 32; i += nt) {
        int lane = i & 31, kt = (i >> 5) & 3, ntg = i >> 7;
        int o = ntg * 8 + (lane >> 2);
        int k0 = kt * 16 + 2 * (lane & 3);
        const float* row = (o < 128) ? &Wv0[o * 65] : &Wc0[(o - 128) * 65];
        float w00 = row[k0 + 1], w01 = row[k0 + 2];
        float w10 = row[k0 + 9], w11 = row[k0 + 10];
        uint4 f;
        f.x = (unsigned)bf16_hi_u(w00) | ((unsigned)bf16_hi_u(w01) << 16);
        f.y = (unsigned)bf16_hi_u(w10) | ((unsigned)bf16_hi_u(w11) << 16);
        f.z = (unsigned)bf16_lo_u(w00) | ((unsigned)bf16_lo_u(w01) << 16);
        f.w = (unsigned)bf16_lo_u(w10) | ((unsigned)bf16_lo_u(w11) << 16);
        g_W0Frag[i] = f;
    }
    // W1 frags (K=128)
    for (int i = tid; i < 32 * 8 * 32; i += nt) {
        int lane = i & 31, kt = (i >> 5) & 7, ntg = i >> 8;
        int o = ntg * 8 + (lane >> 2);
        int k0 = kt * 16 + 2 * (lane & 3);
        const float* row = (o < 128) ? &Wv1[o * 128] : &Wc1[(o - 128) * 128];
        float w00 = row[k0], w01 = row[k0 + 1], w10 = row[k0 + 8], w11 = row[k0 + 9];
        uint4 f;
        f.x = (unsigned)bf16_hi_u(w00) | ((unsigned)bf16_hi_u(w01) << 16);
        f.y = (unsigned)bf16_hi_u(w10) | ((unsigned)bf16_hi_u(w11) << 16);
        f.z = (unsigned)bf16_lo_u(w00) | ((unsigned)bf16_lo_u(w01) << 16);
        f.w = (unsigned)bf16_lo_u(w10) | ((unsigned)bf16_lo_u(w11) << 16);
        g_W1Frag[i] = f;
    }
    // Wv2 frags (K=128, N=64)
    for (int i = tid; i < 8 * 8 * 32; i += nt) {
        int lane = i & 31, kt = (i >> 5) & 7, ntg = i >> 8;
        int o = ntg * 8 + (lane >> 2);
        int k0 = kt * 16 + 2 * (lane & 3);
        const float* row = &Wv2[o * 128];
        float w00 = row[k0], w01 = row[k0 + 1], w10 = row[k0 + 8], w11 = row[k0 + 9];
        uint4 f;
        f.x = (unsigned)bf16_hi_u(w00) | ((unsigned)bf16_hi_u(w01) << 16);
        f.y = (unsigned)bf16_hi_u(w10) | ((unsigned)bf16_hi_u(w11) << 16);
        f.z = (unsigned)bf16_lo_u(w00) | ((unsigned)bf16_lo_u(w01) << 16);
        f.w = (unsigned)bf16_lo_u(w10) | ((unsigned)bf16_lo_u(w11) << 16);
        g_Wv2Frag[i] = f;
    }
    // Wc2 frags (K=128, N=2048)
    for (int i = tid; i < 256 * 8 * 32; i += nt) {
        int lane = i & 31, kt = (i >> 5) & 7, ntg = i >> 8;
        int n = ntg * 8 + (lane >> 2);
        int k0 = kt * 16 + 2 * (lane & 3);
        const float* wr = Wc2 + (size_t)n * 128;
        float w00 = wr[k0], w01 = wr[k0 + 1], w10 = wr[k0 + 8], w11 = wr[k0 + 9];
        uint4 f;
        f.x = (unsigned)bf16_hi_u(w00) | ((unsigned)bf16_hi_u(w01) << 16);
        f.y = (unsigned)bf16_hi_u(w10) | ((unsigned)bf16_hi_u(w11) << 16);
        f.z = (unsigned)bf16_lo_u(w00) | ((unsigned)bf16_lo_u(w01) << 16);
        f.w = (unsigned)bf16_lo_u(w10) | ((unsigned)bf16_lo_u(w11) << 16);
        g_WcFrag[i] = f;
    }
    for (int i = tid; i < 32 * 128; i += nt) {
        int k = i >> 7, o = i & 127;
        g_Wi0T[i] = Wi0[o * 32 + k];
    }
    for (int i = tid; i < 128 * 128; i += nt) {
        int k = i >> 7, o = i & 127;
        g_Wi1T[i] = Wi1[o * 128 + k];
    }
    for (int i = tid; i < 128 * 64; i += nt) {
        int k = i >> 6, o = i & 63;
        g_Wi2T[i] = Wi2[o * 128 + k];
    }
    for (int o = tid; o < 256; o += nt) {
        const float* row = (o < 128) ? &Wv0[o * 65] : &Wc0[(o - 128) * 65];
        g_w0t[o] = row[0];
        g_b0[o] = (o < 128) ? bv0[o] : bc0[o - 128];
        g_b1[o] = (o < 128) ? bv1[o] : bc1[o - 128];
    }
    for (int i = tid; i < 64 * 8; i += nt) {
        int h = i >> 3, d = i & 7;
        g_WrT[i] = Wr[d * 64 + h];
    }
}

// fast, accurate-enough transcendentals (abs err ~1e-6)
__device__ __forceinline__ float tanh_fast(float x) {
    float e = __expf(2.0f * x);
    return 1.0f - __fdividef(2.0f, 1.0f + e);
}
__device__ __forceinline__ float lipswish(float x) {
    return 0.909f * __fdividef(x, 1.0f + __expf(-x));
}

#define LDSM4(r0, r1, r2, r3, addr) \
    asm volatile("ldmatrix.sync.aligned.m8n8.x4.shared.b16 {%0,%1,%2,%3}, [%4];" \
        : "=r"(r0), "=r"(r1), "=r"(r2), "=r"(r3) : "r"(addr))

#define MMA_BF16(d, a0, a1, a2, a3, b0, b1) \
    asm volatile("mma.sync.aligned.m16n8k16.row.col.f32.bf16.bf16.f32 " \
        "{%0,%1,%2,%3}, {%4,%5,%6,%7}, {%8,%9}, {%0,%1,%2,%3};" \
        : "+f"(d[0]), "+f"(d[1]), "+f"(d[2]), "+f"(d[3]) \
        : "r"(a0), "r"(a1), "r"(a2), "r"(a3), "r"(b0), "r"(b1))

__global__ void __launch_bounds__(NTHR, 1) sde_kernel(
    const float* __restrict__ ts, const float* __restrict__ init_noise,
    const float* __restrict__ bm,
    const float* __restrict__ bi0, const float* __restrict__ bi1, const float* __restrict__ bi2,
    const float* __restrict__ scale_v, const float* __restrict__ bv2,
    const float* __restrict__ scale_c, const float* __restrict__ bc2,
    const float* __restrict__ br, float* __restrict__ out)
{
    __shared__ float y_s[BT][64];                                             // 3584 B
    __shared__ __align__(16) __nv_bfloat16 yhi_s [16][72],  ylo_s [16][72];   // 4608 B
    __shared__ __align__(16) __nv_bfloat16 h1hi_s[16][264], h1lo_s[16][264];  // 16896 B (full 256 cols)
    __shared__ __align__(16) __nv_bfloat16 hvhi_s[16][136], hvlo_s[16][136];  // 8704 B
    __shared__ __align__(16) __nv_bfloat16 Ahi_s [16][136], Alo_s [16][136];  // 8704 B
    __shared__ float diff_s[64][15];                                          // 3840 B
    __shared__ float bm_s  [16][33];                                          // 2112 B
    // total 48448 B <= 48 KB

    const int tid  = threadIdx.x;
    const int b0g  = blockIdx.x * BT;
    int nb = BATCH - b0g; if (nb > BT) nb = BT;
    const float ts0 = ts[0];

    const int lane = tid & 31;
    const int wrp  = tid >> 5;                 // 0..15
    const int t    = lane & 3;
    const int g    = lane >> 2;
    const int lrow = lane & 15;
    const int kofs = (lane & 16) ? 8 : 0;
    const unsigned aY   = (unsigned)__cvta_generic_to_shared(&yhi_s [0][0]) + (lrow * 72  + kofs) * 2;
    const unsigned aYl  = (unsigned)__cvta_generic_to_shared(&ylo_s [0][0]) + (lrow * 72  + kofs) * 2;
    const unsigned aH1base  = (unsigned)__cvta_generic_to_shared(&h1hi_s[0][0]) + (lrow * 264 + kofs) * 2;
    const unsigned aH1lbase = (unsigned)__cvta_generic_to_shared(&h1lo_s[0][0]) + (lrow * 264 + kofs) * 2;
    const unsigned aH1  = aH1base  + ((wrp < 8) ? 0 : 256);   // c-warps contract h1 cols [128,256)
    const unsigned aH1l = aH1lbase + ((wrp < 8) ? 0 : 256);
    const unsigned aHv  = (unsigned)__cvta_generic_to_shared(&hvhi_s[0][0]) + (lrow * 136 + kofs) * 2;
    const unsigned aHvl = (unsigned)__cvta_generic_to_shared(&hvlo_s[0][0]) + (lrow * 136 + kofs) * 2;
    const unsigned aA   = (unsigned)__cvta_generic_to_shared(&Ahi_s [0][0]) + (lrow * 136 + kofs) * 2;
    const unsigned aAl  = (unsigned)__cvta_generic_to_shared(&Alo_s [0][0]) + (lrow * 136 + kofs) * 2;

    // step-invariant per-thread epilogue constants (registers)
    const int oB0 = wrp * 16 + 2 * t;      // phase B/C q=0 columns oB0, oB0+1
    const int oB1 = oB0 + 8;               // q=1 columns
    const float w0t00 = g_w0t[oB0], w0t01 = g_w0t[oB0 + 1];
    const float w0t10 = g_w0t[oB1], w0t11 = g_w0t[oB1 + 1];
    const float b000 = g_b0[oB0], b001 = g_b0[oB0 + 1];
    const float b010 = g_b0[oB1], b011 = g_b0[oB1 + 1];
    const float b100 = g_b1[oB0], b101 = g_b1[oB0 + 1];
    const float b110 = g_b1[oB1], b111 = g_b1[oB1 + 1];
    const int oD = (wrp & 7) * 8 + 2 * t;   // phase D columns (only used when wrp<8)
    const float bv20 = bv2[oD], bv21 = bv2[oD + 1];
    const float sv0  = scale_v[oD], sv1 = scale_v[oD + 1];

    // ---------------- initial MLP: init_noise -> y0 ----------------
    {
        float* nbuf = (float*)diff_s;   // [16][32] staging (2048 B <= 3840 B)
        for (int i = tid; i < 16 * 32; i += NTHR) {
            int b = i >> 5, z = i & 31;
            nbuf[i] = (b < nb) ? init_noise[(size_t)(b0g + b) * INZ + z] : 0.0f;
        }
        __syncthreads();
        {   // L0: 32 -> 128, relu -> h1 hi/lo (cols 0..127)
            int o = tid & 127, gg = tid >> 7;
            float acc[4];
            float bias = bi0[o];
            #pragma unroll
            for (int j = 0; j < 4; j++) acc[j] = bias;
            for (int k = 0; k < 32; k++) {
                float w = g_Wi0T[k * 128 + o];
                #pragma unroll
                for (int j = 0; j < 4; j++) acc[j] = fmaf(w, nbuf[(gg * 4 + j) * 32 + k], acc[j]);
            }
            #pragma unroll
            for (int j = 0; j < 4; j++) {
                float v = fmaxf(acc[j], 0.0f);
                __nv_bfloat16 h = __float2bfloat16(v);
                h1hi_s[gg * 4 + j][o] = h;
                h1lo_s[gg * 4 + j][o] = __float2bfloat16(v - __bfloat162float(h));
            }
        }
        __syncthreads();
        {   // L1: 128 -> 128, relu -> hv hi/lo
            int o = tid & 127, gg = tid >> 7;
            float acc[4];
            float bias = bi1[o];
            #pragma unroll
            for (int j = 0; j < 4; j++) acc[j] = bias;
            for (int k = 0; k < 128; k++) {
                float w = g_Wi1T[k * 128 + o];
                #pragma unroll
                for (int j = 0; j < 4; j++) {
                    float a = __bfloat162float(h1hi_s[gg * 4 + j][k]) +
                              __bfloat162float(h1lo_s[gg * 4 + j][k]);
                    acc[j] = fmaf(w, a, acc[j]);
                }
            }
            #pragma unroll
            for (int j = 0; j < 4; j++) {
                float v = fmaxf(acc[j], 0.0f);
                __nv_bfloat16 h = __float2bfloat16(v);
                hvhi_s[gg * 4 + j][o] = h;
                hvlo_s[gg * 4 + j][o] = __float2bfloat16(v - __bfloat162float(h));
            }
        }
        __syncthreads();
        {   // L2: 128 -> 64, identity -> y0 (fp32 + hi/lo; rows 14,15 zeroed)
            int o = tid & 63, gg = tid >> 6;
            float bias = bi2[o];
            float a0 = bias, a1 = bias;
            for (int k = 0; k < 128; k++) {
                float w = g_Wi2T[k * 64 + o];
                float x0 = __bfloat162float(hvhi_s[gg * 2 + 0][k]) + __bfloat162float(hvlo_s[gg * 2 + 0][k]);
                float x1 = __bfloat162float(hvhi_s[gg * 2 + 1][k]) + __bfloat162float(hvlo_s[gg * 2 + 1][k]);
                a0 = fmaf(w, x0, a0);
                a1 = fmaf(w, x1, a1);
            }
            #pragma unroll
            for (int jj = 0; jj < 2; jj++) {
                int b = gg * 2 + jj;
                float v = jj ? a1 : a0;
                if (b < BT) {
                    y_s[b][o] = v;
                    __nv_bfloat16 h = __float2bfloat16(v);
                    yhi_s[b][o] = h;
                    ylo_s[b][o] = __float2bfloat16(v - __bfloat162float(h));
                } else {
                    yhi_s[b][o] = __float2bfloat16(0.0f);
                    ylo_s[b][o] = __float2bfloat16(0.0f);
                }
            }
        }
        __syncthreads();
    }

    // ---------------- time scan ----------------
    for (int step = 0; step < STEPS; step++) {
        // stage noise
        for (int i = tid; i < BT * 32; i += NTHR) {
            int b = i >> 5, z = i & 31;
            bm_s[b][z] = (b < nb)
                ? bm[(size_t)(b0g + b) * (STEPS * NZv) + step * NZv + z] : 0.0f;
        }
        const float tcur = ts0 + (float)step;
        // ---- phase B: layer0 (256 outputs, K=64 mma; t-column + bias in epilogue) ----
        {
            float acc[2][4];
            #pragma unroll
            for (int q = 0; q < 2; q++)
                #pragma unroll
                for (int r = 0; r < 4; r++) acc[q][r] = 0.0f;
            #pragma unroll
            for (int kt = 0; kt < 4; kt++) {
                unsigned ah0, ah1, ah2, ah3, al0, al1, al2, al3;
                LDSM4(ah0, ah1, ah2, ah3, aY  + kt * 32);
                LDSM4(al0, al1, al2, al3, aYl + kt * 32);
                #pragma unroll
                for (int q = 0; q < 2; q++) {
                    uint4 W = __ldg(&g_W0Frag[(((wrp * 2 + q) * 4) + kt) * 32 + lane]);
                    MMA_BF16(acc[q], ah0, ah1, ah2, ah3, W.x, W.y);
                    MMA_BF16(acc[q], ah0, ah1, ah2, ah3, W.z, W.w);
                    MMA_BF16(acc[q], al0, al1, al2, al3, W.x, W.y);
                }
            }
            #pragma unroll
            for (int q = 0; q < 2; q++) {
                int o0 = (q == 0) ? oB0 : oB1;
                float bia0 = fmaf((q == 0) ? w0t00 : w0t10, tcur, (q == 0) ? b000 : b010);
                float bia1 = fmaf((q == 0) ? w0t01 : w0t11, tcur, (q == 0) ? b001 : b011);
                float v00 = lipswish(acc[q][0] + bia0);
                float v01 = lipswish(acc[q][1] + bia1);
                float v10 = lipswish(acc[q][2] + bia0);
                float v11 = lipswish(acc[q][3] + bia1);
                __nv_bfloat16 h00 = __float2bfloat16(v00), h01 = __float2bfloat16(v01);
                __nv_bfloat16 h10 = __float2bfloat16(v10), h11 = __float2bfloat16(v11);
                h1hi_s[g][o0] = h00;          h1lo_s[g][o0] = __float2bfloat16(v00 - __bfloat162float(h00));
                h1hi_s[g][o0 + 1] = h01;      h1lo_s[g][o0 + 1] = __float2bfloat16(v01 - __bfloat162float(h01));
                h1hi_s[g + 8][o0] = h10;      h1lo_s[g + 8][o0] = __float2bfloat16(v10 - __bfloat162float(h10));
                h1hi_s[g + 8][o0 + 1] = h11;  h1lo_s[g + 8][o0 + 1] = __float2bfloat16(v11 - __bfloat162float(h11));
            }
        }
        __syncthreads();
        // ---- phase C: layer1 (256 outputs, K=128 mma; c-warps read h1 cols [128,256)) ----
        {
            float acc[2][4];
            #pragma unroll
            for (int q = 0; q < 2; q++)
                #pragma unroll
                for (int r = 0; r < 4; r++) acc[q][r] = 0.0f;
            #pragma unroll
            for (int kt = 0; kt < 8; kt++) {
                unsigned ah0, ah1, ah2, ah3, al0, al1, al2, al3;
                LDSM4(ah0, ah1, ah2, ah3, aH1  + kt * 32);
                LDSM4(al0, al1, al2, al3, aH1l + kt * 32);
                #pragma unroll
                for (int q = 0; q < 2; q++) {
                    uint4 W = __ldg(&g_W1Frag[(((wrp * 2 + q) * 8) + kt) * 32 + lane]);
                    MMA_BF16(acc[q], ah0, ah1, ah2, ah3, W.x, W.y);
                    MMA_BF16(acc[q], ah0, ah1, ah2, ah3, W.z, W.w);
                    MMA_BF16(acc[q], al0, al1, al2, al3, W.x, W.y);
                }
            }
            #pragma unroll
            for (int q = 0; q < 2; q++) {
                int o0 = (q == 0) ? oB0 : oB1, o1 = o0 + 1;
                float v00 = lipswish(acc[q][0] + ((q == 0) ? b100 : b110));
                float v01 = lipswish(acc[q][1] + ((q == 0) ? b101 : b111));
                float v10 = lipswish(acc[q][2] + ((q == 0) ? b100 : b110));
                float v11 = lipswish(acc[q][3] + ((q == 0) ? b101 : b111));
                __nv_bfloat16 h00 = __float2bfloat16(v00), h01 = __float2bfloat16(v01);
                __nv_bfloat16 h10 = __float2bfloat16(v10), h11 = __float2bfloat16(v11);
                if (wrp < 8) {   // v-half -> hv  (o in [0,128))
                    hvhi_s[g][o0] = h00;      hvlo_s[g][o0] = __float2bfloat16(v00 - __bfloat162float(h00));
                    hvhi_s[g][o1] = h01;      hvlo_s[g][o1] = __float2bfloat16(v01 - __bfloat162float(h01));
                    hvhi_s[g + 8][o0] = h10;  hvlo_s[g + 8][o0] = __float2bfloat16(v10 - __bfloat162float(h10));
                    hvhi_s[g + 8][o1] = h11;  hvlo_s[g + 8][o1] = __float2bfloat16(v11 - __bfloat162float(h11));
                } else {         // c-half -> A (k = o-128)
                    int k0 = o0 - 128, k1 = o1 - 128;
                    Ahi_s[g][k0] = h00;       Alo_s[g][k0] = __float2bfloat16(v00 - __bfloat162float(h00));
                    Ahi_s[g][k1] = h01;       Alo_s[g][k1] = __float2bfloat16(v01 - __bfloat162float(h01));
                    Ahi_s[g + 8][k0] = h10;   Alo_s[g + 8][k0] = __float2bfloat16(v10 - __bfloat162float(h10));
                    Ahi_s[g + 8][k1] = h11;   Alo_s[g + 8][k1] = __float2bfloat16(v11 - __bfloat162float(h11));
                }
            }
        }
        __syncthreads();
        // ---- phase D: drift head (64 outputs, K=128 mma), warps 0..7; y updated in place ----
        if (wrp < 8) {
            float acc[4] = {0.0f, 0.0f, 0.0f, 0.0f};
            #pragma unroll
            for (int kt = 0; kt < 8; kt++) {
                unsigned ah0, ah1, ah2, ah3, al0, al1, al2, al3;
                LDSM4(ah0, ah1, ah2, ah3, aHv  + kt * 32);
                LDSM4(al0, al1, al2, al3, aHvl + kt * 32);
                uint4 W = __ldg(&g_Wv2Frag[(wrp * 8 + kt) * 32 + lane]);
                MMA_BF16(acc, ah0, ah1, ah2, ah3, W.x, W.y);
                MMA_BF16(acc, ah0, ah1, ah2, ah3, W.z, W.w);
                MMA_BF16(acc, al0, al1, al2, al3, W.x, W.y);
            }
            if (g < BT) {
                y_s[g][oD]     += sv0 * tanh_fast(acc[0] + bv20);
                y_s[g][oD + 1] += sv1 * tanh_fast(acc[1] + bv21);
            }
            if (g + 8 < BT) {
                y_s[g + 8][oD]     += sv0 * tanh_fast(acc[2] + bv20);
                y_s[g + 8][oD + 1] += sv1 * tanh_fast(acc[3] + bv21);
            }
        }
        // ---- phase E: controlled field mma (as R10, kt-outer over h-pairs) ----
        #pragma unroll 1
        for (int pass = 0; pass < 2; pass++) {
            const int h0 = wrp * 4 + pass * 2;
            float acc[2][4][4];
            #pragma unroll
            for (int hp = 0; hp < 2; hp++)
                #pragma unroll
                for (int q = 0; q < 4; q++)
                    #pragma unroll
                    for (int r = 0; r < 4; r++) acc[hp][q][r] = 0.0f;
            #pragma unroll
            for (int kt = 0; kt < 8; kt++) {
                unsigned ah0, ah1, ah2, ah3, al0, al1, al2, al3;
                LDSM4(ah0, ah1, ah2, ah3, aA  + kt * 32);
                LDSM4(al0, al1, al2, al3, aAl + kt * 32);
                #pragma unroll
                for (int hp = 0; hp < 2; hp++) {
                    #pragma unroll
                    for (int q = 0; q < 4; q++) {
                        uint4 W = __ldcg(&g_WcFrag[((((h0 + hp) * 4 + q) * 8) + kt) * 32 + lane]);
                        MMA_BF16(acc[hp][q], ah0, ah1, ah2, ah3, W.x, W.y);
                        MMA_BF16(acc[hp][q], ah0, ah1, ah2, ah3, W.z, W.w);
                        MMA_BF16(acc[hp][q], al0, al1, al2, al3, W.x, W.y);
                    }
                }
            }
            #pragma unroll
            for (int hp = 0; hp < 2; hp++) {
                float s0 = 0.0f, s1 = 0.0f;
                #pragma unroll
                for (int q = 0; q < 4; q++) {
                    int n0 = ((h0 + hp) * 4 + q) * 8 + 2 * t;
                    float2 sc = __ldg((const float2*)&scale_c[n0]);
                    float2 bc = __ldg((const float2*)&bc2[n0]);
                    int nz0 = n0 & 31;
                    float t0 = sc.x * tanh_fast(acc[hp][q][0] + bc.x);
                    float t1 = sc.y * tanh_fast(acc[hp][q][1] + bc.y);
                    float t2 = sc.x * tanh_fast(acc[hp][q][2] + bc.x);
                    float t3 = sc.y * tanh_fast(acc[hp][q][3] + bc.y);
                    s0 = fmaf(t0, bm_s[g][nz0],     fmaf(t1, bm_s[g][nz0 + 1],     s0));
                    s1 = fmaf(t2, bm_s[g + 8][nz0], fmaf(t3, bm_s[g + 8][nz0 + 1], s1));
                }
                s0 += __shfl_xor_sync(0xffffffffu, s0, 1);
                s0 += __shfl_xor_sync(0xffffffffu, s0, 2);
                s1 += __shfl_xor_sync(0xffffffffu, s1, 1);
                s1 += __shfl_xor_sync(0xffffffffu, s1, 2);
                if (t == 0) {
                    int h = h0 + hp;
                    diff_s[h][g] = s0;
                    if (g < 6) diff_s[h][g + 8] = s1;
                }
            }
        }
        __syncthreads();
        // ---- phase F: y += diff (fp32 + bf16 hi/lo refresh) ----
        for (int i = tid; i < BT * 64; i += NTHR) {
            int b = i >> 6, h = i & 63;
            float v = y_s[b][h] + diff_s[h][b];
            y_s[b][h] = v;
            __nv_bfloat16 hh = __float2bfloat16(v);
            yhi_s[b][h] = hh;
            ylo_s[b][h] = __float2bfloat16(v - __bfloat162float(hh));
        }
        __syncthreads();
        // ---- readout: out[b, step, :] = y @ Wr^T + br ----
        if (tid < BT * DOUT) {
            int b = tid >> 3, d = tid & 7;
            if (b < nb) {
                float acc = br[d];
                #pragma unroll 8
                for (int h = 0; h < 64; h++)
                    acc = fmaf(y_s[b][h], g_WrT[h * 8 + d], acc);
                out[(size_t)(b0g + b) * (STEPS * DOUT) + step * DOUT + d] = acc;
            }
        }
    }
}

extern "C" void kernel_launch(void* const* d_in, const int* in_sizes, int n_in,
                              void* d_out, int out_size) {
    (void)in_sizes; (void)n_in; (void)out_size;
    const float* ts         = (const float*)d_in[0];
    const float* init_noise = (const float*)d_in[1];
    const float* bm         = (const float*)d_in[2];
    const float* Wi0        = (const float*)d_in[3];
    const float* bi0        = (const float*)d_in[4];
    const float* Wi1        = (const float*)d_in[5];
    const float* bi1        = (const float*)d_in[6];
    const float* Wi2        = (const float*)d_in[7];
    const float* bi2        = (const float*)d_in[8];
    const float* scale_v    = (const float*)d_in[9];
    const float* Wv0        = (const float*)d_in[10];
    const float* bv0        = (const float*)d_in[11];
    const float* Wv1        = (const float*)d_in[12];
    const float* bv1        = (const float*)d_in[13];
    const float* Wv2        = (const float*)d_in[14];
    const float* bv2        = (const float*)d_in[15];
    const float* scale_c    = (const float*)d_in[16];
    const float* Wc0        = (const float*)d_in[17];
    const float* bc0        = (const float*)d_in[18];
    const float* Wc1        = (const float*)d_in[19];
    const float* bc1        = (const float*)d_in[20];
    const float* Wc2        = (const float*)d_in[21];
    const float* bc2        = (const float*)d_in[22];
    const float* Wr         = (const float*)d_in[23];
    const float* br         = (const float*)d_in[24];
    float* out = (float*)d_out;

    prep_kernel<<<256, 256>>>(Wi0, Wi1, Wi2, Wv0, bv0, Wv1, bv1, Wv2,
                              Wc0, bc0, Wc1, bc1, Wc2, Wr);
    sde_kernel<<<NCTA, NTHR>>>(ts, init_noise, bm, bi0, bi1, bi2,
                               scale_v, bv2, scale_c, bc2, br, out);
}